// round 13
// baseline (speedup 1.0000x reference)
#include <cuda_runtime.h>

// Problem shape: B = 16384 rows, N = 64 neighbors, D = 64, H = 128
#define BROWS 16384

__device__ float g_C[BROWS * 128];     // [node_f | neigh_agg] per row
// Classifier weight in tf32 B-fragment layout (tile kt 0..31, nt 0..15)
__device__ float2 g_WF[512 * 32];

typedef unsigned long long u64;
typedef unsigned int u32;

// ---------------- helpers ----------------
__device__ __forceinline__ float tanh_fast(float x) {
    float y; asm("tanh.approx.f32 %0, %1;" : "=f"(y) : "f"(x)); return y;
}
__device__ __forceinline__ u32 to_tf32(float x) {
    u32 r; asm("cvt.rna.tf32.f32 %0, %1;" : "=r"(r) : "f"(x)); return r;
}
// m16n8k8 tf32 MMA: D = A(16x8,row) * B(8x8,col) + D, fp32 accum
__device__ __forceinline__ void mma8(float* c, const u32* a, u32 b0, u32 b1) {
    asm("mma.sync.aligned.m16n8k8.row.col.f32.tf32.tf32.f32 "
        "{%0,%1,%2,%3}, {%4,%5,%6,%7}, {%8,%9}, {%0,%1,%2,%3};"
        : "+f"(c[0]), "+f"(c[1]), "+f"(c[2]), "+f"(c[3])
        : "r"(a[0]), "r"(a[1]), "r"(a[2]), "r"(a[3]), "r"(b0), "r"(b1));
}
// row-group barrier: syncs the 4 warps (128 threads) owning `row`
__device__ __forceinline__ void bar_row(int row) {
    asm volatile("bar.sync %0, 128;" :: "r"(row + 1) : "memory");
}

// ---------------- SMEM layout for k_rows (dynamic, bytes) ----------------
#define FPITCH      68
#define OFF_F       0                         // 2*64*68*4 = 34816
#define OFF_BF      34816                     // W2 B-fragments 16384
#define OFF_W1      51200                     // 16384
#define OFF_P       67584                     // 1024  float4 (tw,tb,nw,2nb)[64]
#define OFF_NF      68608                     // 512   node_f [2][64]
#define OFF_AE      69120                     // 1024  aE halves [2][2][64]
#define OFF_WN      70144                     // 512   w_n [2][64]
#define OFF_DT      70656                     // 512
#define OFF_MF      71168                     // 512
#define OFF_V       71680                     // 256
#define OFF_RED     71936                     // 64 (normN[4] + maskM[8])
#define SMEM_TOTAL  72000

// SMEM for k_gemm: A tile [64][68] floats + B fragments 4096 float2
#define GEMM_SMEM   (64 * 68 * 4 + 4096 * 8)  // 50176

// ---------------- kernel 1: persistent, 256 thr, 2 row pipelines -----------
__global__ __launch_bounds__(256, 3)
void k_rows(const float* __restrict__ dt_node, const float* __restrict__ deg_node,
            const float* __restrict__ cc_node, const float* __restrict__ dt_neigh,
            const float* __restrict__ deg_neigh, const float* __restrict__ cc_neigh,
            const unsigned int* __restrict__ mask,
            const float* __restrict__ t2v_w, const float* __restrict__ t2v_b,
            const float* __restrict__ node_w, const float* __restrict__ node_b,
            const float* __restrict__ W1, const float* __restrict__ W2,
            const float* __restrict__ att_v, const float* __restrict__ Wcls,
            int pairs) {
    extern __shared__ __align__(16) char sm[];
    float*  sF  = (float*)(sm + OFF_F);
    float2* sBF = (float2*)(sm + OFF_BF);
    float*  sW1 = (float*)(sm + OFF_W1);
    float4* sP  = (float4*)(sm + OFF_P);
    float*  sNF = (float*)(sm + OFF_NF);
    float*  sAE = (float*)(sm + OFF_AE);       // [row][half][64]
    float*  sWn = (float*)(sm + OFF_WN);
    float*  sDT = (float*)(sm + OFF_DT);
    float*  sMF = (float*)(sm + OFF_MF);
    float*  sV  = (float*)(sm + OFF_V);
    float*  sRedN = (float*)(sm + OFF_RED);      // [2 rows][2]
    float*  sRedM = (float*)(sm + OFF_RED) + 4;  // [2 rows][4]

    const int t = threadIdx.x;
    const int lane = t & 31, wid = t >> 5;
    const int row = t >> 7;          // row of the pair (0/1)
    const int t2  = t & 127;         // index within row group
    const int nn  = t2 >> 1;         // neighbor (feature stage)
    const int h   = t2 & 1;          // dim-half (feature stage)
    const int wr  = wid & 3;         // warp-in-row
    const int g = lane >> 2, tq = lane & 3;

    // ---- fold-in: classifier weight -> tf32 B-fragment layout (once) ----
    for (int e = blockIdx.x * 256 + t; e < 512 * 32; e += gridDim.x * 256) {
        int tile = e >> 5, ln = e & 31;
        int kt = tile >> 4, nt = tile & 15;
        int gg = ln >> 2, tqq = ln & 3;
        const float* wrp = Wcls + (nt * 8 + gg) * 256 + kt * 8 + tqq;
        float2 v;
        v.x = __uint_as_float(to_tf32(wrp[0]));
        v.y = __uint_as_float(to_tf32(wrp[4]));
        g_WF[e] = v;
    }

    // ---- one-time init ----
    {   // W1 plain [d][e]: 1024 float4
        const float4* src = (const float4*)W1;
        float4* dst = (float4*)sW1;
#pragma unroll
        for (int i = 0; i < 4; ++i) dst[t + i * 256] = src[t + i * 256];
    }
    // W2 -> B fragments (tf32): 2048 entries
#pragma unroll
    for (int i = 0; i < 8; ++i) {
        int e = t + i * 256;
        int tile = e >> 5, ln = e & 31;
        int kt = tile >> 3, nt = tile & 7;
        int gg = ln >> 2, tqq = ln & 3;
        int d = kt * 8 + tqq, ee = nt * 8 + gg;
        float2 v;
        v.x = __uint_as_float(to_tf32(W2[d * 64 + ee]));
        v.y = __uint_as_float(to_tf32(W2[(d + 4) * 64 + ee]));
        sBF[tile * 32 + ln] = v;
    }
    if (t < 64) {
        sV[t] = att_v[t];
        sP[t] = make_float4(t2v_w[t], t2v_b[t], node_w[t], 2.0f * node_b[t]);
    }
    __syncthreads();

    // ---- prefetch first iteration ----
    int p = blockIdx.x;
    float pv_tn = 0.f, pv_dcn = 0.f, pv_dtn = 0.f, pv_dc = 0.f;
    u32 pv_mk = 0;
    {
        int b = p * 2 + row;
        pv_tn  = fabsf(dt_node[b]);
        pv_dcn = deg_node[b] + cc_node[b];
        pv_dtn = dt_neigh[b * 64 + nn];
        pv_dc  = deg_neigh[b * 64 + nn] + cc_neigh[b * 64 + nn];
        pv_mk  = mask[b * 64 + nn];
    }

    for (; p < pairs; p += gridDim.x) {
        const int b = p * 2 + row;
        const float c_tn = pv_tn, c_dcn = pv_dcn;
        const float c_dtn = pv_dtn, c_dc = pv_dc;
        const u32 c_mk = pv_mk;

        // ---- stage 1: node-feature partial (t2<64) + mask count (all) ----
        float fb = 0.f;
        if (t2 < 64) {                         // warps wr=0,1: uniform branch
            float4 P = sP[t2];
            float vv0 = c_tn * P.x + P.y;
            float cv = (t2 == 0) ? vv0 : __cosf(vv0);
            fb = cv + fmaf(c_dcn, P.z, P.w);
            float ss = fb * fb;
#pragma unroll
            for (int off = 16; off > 0; off >>= 1)
                ss += __shfl_xor_sync(0xffffffffu, ss, off);
            if (lane == 0) sRedN[row * 2 + wr] = ss;
        }
        const float mfv = (h == 0 && c_mk) ? 1.0f : 0.0f;
        {
            float ms = mfv;
#pragma unroll
            for (int off = 16; off > 0; off >>= 1)
                ms += __shfl_xor_sync(0xffffffffu, ms, off);
            if (lane == 0) sRedM[row * 4 + wr] = ms;
        }
        bar_row(row);                                      // (A) + reuse guard
        const float rnin = 1.0f /
            fmaxf((sRedM[row * 4] + sRedM[row * 4 + 1]) +
                  (sRedM[row * 4 + 2] + sRedM[row * 4 + 3]), 1.0f);
        if (t2 < 64) {
            float inv = rsqrtf(fmaxf(sRedN[row * 2] + sRedN[row * 2 + 1], 1e-24f));
            sNF[row * 64 + t2] = fb * inv;
        }
        if (h == 0) { sDT[row * 64 + nn] = c_dtn; sMF[row * 64 + nn] = mfv; }

        // ---- stage 2: neighbor feature, 2 threads per neighbor ----
        {
            float ta = fabsf(c_dtn);
            const int d0 = h * 32;
            float f[32]; float s0 = 0.f, s1 = 0.f, s2a = 0.f, s3 = 0.f;
#pragma unroll
            for (int j = 0; j < 32; j += 4) {
                float4 P0 = sP[d0 + j], P1 = sP[d0 + j + 1];
                float4 P2 = sP[d0 + j + 2], P3 = sP[d0 + j + 3];
                float v0 = ta * P0.x + P0.y;
                float v1 = ta * P1.x + P1.y;
                float v2 = ta * P2.x + P2.y;
                float v3 = ta * P3.x + P3.y;
                float c0 = (d0 + j == 0) ? v0 : __cosf(v0);
                float c1 = __cosf(v1), c2 = __cosf(v2), c3 = __cosf(v3);
                float x0 = c0 + fmaf(c_dc, P0.z, P0.w);
                float x1 = c1 + fmaf(c_dc, P1.z, P1.w);
                float x2 = c2 + fmaf(c_dc, P2.z, P2.w);
                float x3 = c3 + fmaf(c_dc, P3.z, P3.w);
                f[j] = x0; f[j + 1] = x1; f[j + 2] = x2; f[j + 3] = x3;
                s0 += x0 * x0; s1 += x1 * x1; s2a += x2 * x2; s3 += x3 * x3;
            }
            float s = (s0 + s1) + (s2a + s3);
            s += __shfl_xor_sync(0xffffffffu, s, 1);       // partner half
            float inv2 = rsqrtf(fmaxf(s, 1e-24f));
            float* frow = sF + (row * 64 + nn) * FPITCH + d0;
#pragma unroll
            for (int q = 0; q < 8; ++q) {
                float4 v4;
                v4.x = __uint_as_float(to_tf32(f[4 * q + 0] * inv2));
                v4.y = __uint_as_float(to_tf32(f[4 * q + 1] * inv2));
                v4.z = __uint_as_float(to_tf32(f[4 * q + 2] * inv2));
                v4.w = __uint_as_float(to_tf32(f[4 * q + 3] * inv2));
                *(float4*)(frow + 4 * q) = v4;
            }
        }
        bar_row(row);                                      // (B) sF/sNF/sDT/sMF

        // ---- prefetch next iteration ----
        {
            int pn = p + gridDim.x;
            if (pn < pairs) {
                int bn = pn * 2 + row;
                pv_tn  = fabsf(dt_node[bn]);
                pv_dcn = deg_node[bn] + cc_node[bn];
                pv_dtn = dt_neigh[bn * 64 + nn];
                pv_dc  = deg_neigh[bn * 64 + nn] + cc_neigh[bn * 64 + nn];
                pv_mk  = mask[bn * 64 + nn];
            }
        }

        // ---- stage 3: aE half-dot: e = t2&63, d-half = t2>>6 ----
        {
            const int e = t2 & 63, h2 = t2 >> 6;
            const float* nf = sNF + row * 64 + h2 * 32;
            const float* w1 = sW1 + h2 * 32 * 64 + e;
            float a0 = 0.f, a1 = 0.f, a2 = 0.f, a3 = 0.f;
#pragma unroll
            for (int d = 0; d < 32; d += 4) {
                a0 += nf[d]     * w1[d * 64];
                a1 += nf[d + 1] * w1[(d + 1) * 64];
                a2 += nf[d + 2] * w1[(d + 2) * 64];
                a3 += nf[d + 3] * w1[(d + 3) * 64];
            }
            sAE[row * 128 + h2 * 64 + e] = (a0 + a1) + (a2 + a3);
        }
        bar_row(row);                                      // (C) sAE visible

        // ---- stage 4: MMA, warp owns 16 neighbors (1 M-tile) x 64e x 64d ---
        float cacc[8][4];
#pragma unroll
        for (int nt = 0; nt < 8; ++nt)
#pragma unroll
            for (int c = 0; c < 4; ++c) cacc[nt][c] = 0.f;

        const float* fbase = sF + (row * 64 + wr * 16) * FPITCH;
#pragma unroll
        for (int kt = 0; kt < 8; ++kt) {
            u32 a[4];
            const float* ap = fbase + kt * 8;
            a[0] = __float_as_uint(ap[g * FPITCH + tq]);
            a[1] = __float_as_uint(ap[(g + 8) * FPITCH + tq]);
            a[2] = __float_as_uint(ap[g * FPITCH + tq + 4]);
            a[3] = __float_as_uint(ap[(g + 8) * FPITCH + tq + 4]);
#pragma unroll
            for (int nt = 0; nt < 8; ++nt) {
                float2 bb = sBF[(kt * 8 + nt) * 32 + lane];
                mma8(cacc[nt], a, __float_as_uint(bb.x), __float_as_uint(bb.y));
            }
        }

        // ---- stage 5: fused epilogue att -> score -> w_n ----
        {
            const float* aE0 = sAE + row * 128;
            float av0 = 0.f, av1 = 0.f;
#pragma unroll
            for (int nt = 0; nt < 8; ++nt) {
                int e0 = nt * 8 + 2 * tq;
                float v0 = sV[e0], v1 = sV[e0 + 1];
                float a0 = aE0[e0] + aE0[64 + e0];
                float a1 = aE0[e0 + 1] + aE0[64 + e0 + 1];
                av0 += v0 * tanh_fast(a0 + cacc[nt][0])
                     + v1 * tanh_fast(a1 + cacc[nt][1]);
                av1 += v0 * tanh_fast(a0 + cacc[nt][2])
                     + v1 * tanh_fast(a1 + cacc[nt][3]);
            }
#pragma unroll
            for (int r2 = 0; r2 < 2; ++r2) {
                float x = (r2 == 0) ? av0 : av1;
                x += __shfl_xor_sync(0xffffffffu, x, 1);
                x += __shfl_xor_sync(0xffffffffu, x, 2);
                if (tq == 0) {
                    int n = wr * 16 + r2 * 8 + g;
                    float dtv = sDT[row * 64 + n];
                    float ts = 1.0f / (1.0f + 2.0f * dtv);   // Decayer(2,'rev')
                    float ls = (ts > 0.f) ? ts : 0.01f * ts; // leaky_relu
                    sWn[row * 64 + n] = sMF[row * 64 + n] * ls * x * rnin;
                }
            }
        }
        bar_row(row);                                      // (D) sWn visible

        // ---- stage 6: aggregation (t2<64, d=t2) + output ----
        if (t2 < 64) {
            const int d = t2;
            float a0 = 0.f, a1 = 0.f, a2 = 0.f, a3 = 0.f;
            const float* fr = sF + row * 64 * FPITCH;
            const float* wn = sWn + row * 64;
#pragma unroll
            for (int n = 0; n < 64; n += 4) {
                a0 += wn[n]     * fr[n * FPITCH + d];
                a1 += wn[n + 1] * fr[(n + 1) * FPITCH + d];
                a2 += wn[n + 2] * fr[(n + 2) * FPITCH + d];
                a3 += wn[n + 3] * fr[(n + 3) * FPITCH + d];
            }
            g_C[b * 128 + d] = sNF[row * 64 + d];
            g_C[b * 128 + 64 + d] = (a0 + a1) + (a2 + a3);
        }
        // barrier (A) of next iteration guards sF/sNF/sWn reuse
    }
}

// ---------------- kernel 2: out = relu([g_C | hist] @ W^T), tf32 MMA -------
// M=16384, N=128, K=256. CTA tile 64x128, BK=64, 256 threads (8 warps).
__global__ __launch_bounds__(256)
void k_gemm(const float* __restrict__ hist, float* __restrict__ out) {
    extern __shared__ __align__(16) float sg[];
    float* sA = sg;                        // [64][68]
    float2* sB = (float2*)(sg + 64 * 68);  // 128 tiles * 32 lanes per K-block

    const int m0 = blockIdx.x * 64;
    const int t = threadIdx.x;
    const int lane = t & 31, wid = t >> 5;
    const int mt_row = wid >> 1, nhalf = wid & 1;
    const int g = lane >> 2, tq = lane & 3;

    float acc[8][4];
#pragma unroll
    for (int nt = 0; nt < 8; ++nt)
#pragma unroll
        for (int c = 0; c < 4; ++c) acc[nt][c] = 0.f;

#pragma unroll
    for (int kb = 0; kb < 4; ++kb) {
        const float* src = (kb < 2) ? g_C : hist;
        const int koff = (kb & 1) * 64;
        __syncthreads();
#pragma unroll
        for (int i = 0; i < 4; ++i) {
            int s = t + i * 256;
            int r = s >> 4, k4 = (s & 15) * 4;
            float4 v = *(const float4*)(src + (m0 + r) * 128 + koff + k4);
            float4 w;
            w.x = __uint_as_float(to_tf32(v.x));
            w.y = __uint_as_float(to_tf32(v.y));
            w.z = __uint_as_float(to_tf32(v.z));
            w.w = __uint_as_float(to_tf32(v.w));
            *(float4*)(sA + r * 68 + k4) = w;
        }
        {
            const float4* wf = (const float4*)(g_WF + kb * 4096);
            float4* sb4 = (float4*)sB;
#pragma unroll
            for (int i = 0; i < 8; ++i) sb4[t + i * 256] = wf[t + i * 256];
        }
        __syncthreads();

#pragma unroll
        for (int ktl = 0; ktl < 8; ++ktl) {
            u32 a[4];
            const float* ap = sA + (mt_row * 16) * 68 + ktl * 8;
            a[0] = __float_as_uint(ap[g * 68 + tq]);
            a[1] = __float_as_uint(ap[(g + 8) * 68 + tq]);
            a[2] = __float_as_uint(ap[g * 68 + tq + 4]);
            a[3] = __float_as_uint(ap[(g + 8) * 68 + tq + 4]);
#pragma unroll
            for (int nt = 0; nt < 8; ++nt) {
                float2 bb = sB[(ktl * 16 + nhalf * 8 + nt) * 32 + lane];
                mma8(acc[nt], a, __float_as_uint(bb.x), __float_as_uint(bb.y));
            }
        }
    }

#pragma unroll
    for (int nt = 0; nt < 8; ++nt) {
        int r1 = m0 + mt_row * 16 + g;
        int cc = nhalf * 64 + nt * 8 + 2 * tq;
        float2 lo, hi;
        lo.x = fmaxf(acc[nt][0], 0.f); lo.y = fmaxf(acc[nt][1], 0.f);
        hi.x = fmaxf(acc[nt][2], 0.f); hi.y = fmaxf(acc[nt][3], 0.f);
        *(float2*)(out + r1 * 128 + cc) = lo;
        *(float2*)(out + (r1 + 8) * 128 + cc) = hi;
    }
}

// ---------------------------- launcher --------------------------------------
extern "C" void kernel_launch(void* const* d_in, const int* in_sizes, int n_in,
                              void* d_out, int out_size) {
    const float* dt_node   = (const float*)d_in[0];
    const float* deg_node  = (const float*)d_in[1];
    const float* cc_node   = (const float*)d_in[2];
    const float* dt_neigh  = (const float*)d_in[3];
    const float* deg_neigh = (const float*)d_in[4];
    const float* cc_neigh  = (const float*)d_in[5];
    const unsigned int* mask = (const unsigned int*)d_in[6];
    const float* hist      = (const float*)d_in[7];
    const float* t2v_w     = (const float*)d_in[8];
    const float* t2v_b     = (const float*)d_in[9];
    const float* node_w    = (const float*)d_in[10];
    const float* node_b    = (const float*)d_in[11];
    const float* att_W1    = (const float*)d_in[12];
    const float* att_W2    = (const float*)d_in[13];
    const float* att_v     = (const float*)d_in[14];
    const float* weight    = (const float*)d_in[15];
    float* out = (float*)d_out;

    const int B = in_sizes[0];   // 16384
    const int pairs = B / 2;

    static int smem_set = 0;
    if (!smem_set) {
        cudaFuncSetAttribute(k_rows, cudaFuncAttributeMaxDynamicSharedMemorySize,
                             SMEM_TOTAL);
        cudaFuncSetAttribute(k_gemm, cudaFuncAttributeMaxDynamicSharedMemorySize,
                             GEMM_SMEM);
        smem_set = 1;
    }

    k_rows<<<444, 256, SMEM_TOTAL>>>(dt_node, deg_node, cc_node, dt_neigh,
                                     deg_neigh, cc_neigh, mask, t2v_w, t2v_b,
                                     node_w, node_b, att_W1, att_W2, att_v,
                                     weight, pairs);
    k_gemm<<<B / 64, 256, GEMM_SMEM>>>(hist, out);
}

// round 16
// speedup vs baseline: 1.4522x; 1.4522x over previous
#include <cuda_runtime.h>

// Problem shape: B = 16384 rows, N = 64 neighbors, D = 64, H = 128
#define BROWS 16384

__device__ float g_C[BROWS * 128];     // [node_f | neigh_agg] per row
// Classifier weight in tf32 B-fragment layout (tile kt 0..31, nt 0..15)
__device__ float2 g_WF[512 * 32];

typedef unsigned long long u64;
typedef unsigned int u32;

// ---------------- helpers ----------------
__device__ __forceinline__ float tanh_fast(float x) {
    float y; asm("tanh.approx.f32 %0, %1;" : "=f"(y) : "f"(x)); return y;
}
__device__ __forceinline__ u32 to_tf32(float x) {
    u32 r; asm("cvt.rna.tf32.f32 %0, %1;" : "=r"(r) : "f"(x)); return r;
}
// m16n8k8 tf32 MMA: D = A(16x8,row) * B(8x8,col) + D, fp32 accum
__device__ __forceinline__ void mma8(float* c, const u32* a, u32 b0, u32 b1) {
    asm("mma.sync.aligned.m16n8k8.row.col.f32.tf32.tf32.f32 "
        "{%0,%1,%2,%3}, {%4,%5,%6,%7}, {%8,%9}, {%0,%1,%2,%3};"
        : "+f"(c[0]), "+f"(c[1]), "+f"(c[2]), "+f"(c[3])
        : "r"(a[0]), "r"(a[1]), "r"(a[2]), "r"(a[3]), "r"(b0), "r"(b1));
}
// row-group barrier: syncs only the 2 warps owning `row`
__device__ __forceinline__ void bar_row(int row) {
    asm volatile("bar.sync %0, 64;" :: "r"(row + 1) : "memory");
}

// ---------------- SMEM layout for k_rows (dynamic, bytes) ----------------
#define FPITCH      68
#define OFF_F       0                         // 2*64*68*4 = 34816
#define OFF_BF      34816                     // W2 B-fragments 16384
#define OFF_W1      51200                     // 16384
#define OFF_NF      67584                     // 512  node_f [2][64]
#define OFF_AE      68096                     // 512  a = node_f@W1 [2][64]
#define OFF_ATT     68608                     // 512  att [2][64]
#define OFF_WN      69120                     // 512  w_n [2][64]
#define OFF_V       69632                     // 256
#define OFF_TW      69888
#define OFF_TB      70144
#define OFF_NW      70400
#define OFF_NB      70656
#define OFF_RED     70912                     // 64 (norm[4] + mask[4])
#define SMEM_TOTAL  71168

// SMEM for k_gemm: A tile [64][68] floats + B fragments 4096 float2
#define GEMM_SMEM   (64 * 68 * 4 + 4096 * 8)  // 50176

// ---------------- kernel 1: persistent, 2 independent row pipelines --------
__global__ __launch_bounds__(128, 3)
void k_rows(const float* __restrict__ dt_node, const float* __restrict__ deg_node,
            const float* __restrict__ cc_node, const float* __restrict__ dt_neigh,
            const float* __restrict__ deg_neigh, const float* __restrict__ cc_neigh,
            const unsigned int* __restrict__ mask,
            const float* __restrict__ t2v_w, const float* __restrict__ t2v_b,
            const float* __restrict__ node_w, const float* __restrict__ node_b,
            const float* __restrict__ W1, const float* __restrict__ W2,
            const float* __restrict__ att_v, const float* __restrict__ Wcls,
            int pairs) {
    extern __shared__ __align__(16) char sm[];
    float* sF  = (float*)(sm + OFF_F);
    float2* sBF = (float2*)(sm + OFF_BF);
    float* sW1 = (float*)(sm + OFF_W1);
    float* sNF = (float*)(sm + OFF_NF);
    float* sAE = (float*)(sm + OFF_AE);
    float* sAtt = (float*)(sm + OFF_ATT);
    float* sWn = (float*)(sm + OFF_WN);
    float* sV  = (float*)(sm + OFF_V);
    float* sTW = (float*)(sm + OFF_TW);
    float* sTB = (float*)(sm + OFF_TB);
    float* sNW = (float*)(sm + OFF_NW);
    float* sNB = (float*)(sm + OFF_NB);
    float* sRedN = (float*)(sm + OFF_RED);       // [4] norm partials
    float* sRedM = (float*)(sm + OFF_RED) + 4;   // [4] mask-count partials

    const int t = threadIdx.x;
    const int lane = t & 31, wid = t >> 5;
    const int row = t >> 6;        // which row of the pair (0/1)
    const int dn  = t & 63;        // dim / neighbor index
    const int mrow = wid >> 1, mhalf = wid & 1;
    const int g = lane >> 2, tq = lane & 3;

    // ---- fold-in: classifier weight -> tf32 B-fragment layout (once) ----
    for (int e = blockIdx.x * 128 + t; e < 512 * 32; e += gridDim.x * 128) {
        int tile = e >> 5, ln = e & 31;
        int kt = tile >> 4, nt = tile & 15;
        int gg = ln >> 2, tqq = ln & 3;
        const float* wr = Wcls + (nt * 8 + gg) * 256 + kt * 8 + tqq;
        float2 v;
        v.x = __uint_as_float(to_tf32(wr[0]));
        v.y = __uint_as_float(to_tf32(wr[4]));
        g_WF[e] = v;
    }

    // ---- one-time init ----
    {   // W1 plain [d][e]
        const float4* src = (const float4*)W1;
        float4* dst = (float4*)sW1;
#pragma unroll
        for (int i = 0; i < 8; ++i) dst[t + i * 128] = src[t + i * 128];
    }
    // W2 -> B fragments (tf32)
#pragma unroll
    for (int i = 0; i < 16; ++i) {
        int tile = wid * 16 + i;
        int kt = tile >> 3, nt = tile & 7;
        int d = kt * 8 + tq, e = nt * 8 + g;
        float2 v;
        v.x = __uint_as_float(to_tf32(W2[d * 64 + e]));
        v.y = __uint_as_float(to_tf32(W2[(d + 4) * 64 + e]));
        sBF[tile * 32 + lane] = v;
    }
    if (t < 64) { sV[t] = att_v[t]; sTW[t] = t2v_w[t]; sTB[t] = t2v_b[t];
                  sNW[t] = node_w[t]; sNB[t] = node_b[t]; }
    __syncthreads();

    // ---- prefetch first iteration's inputs ----
    int p = blockIdx.x;
    float pv_tn = 0.f, pv_dcn = 0.f, pv_dtn = 0.f, pv_dc = 0.f;
    u32 pv_mk = 0;
    {
        int b = p * 2 + row;
        pv_tn  = fabsf(dt_node[b]);
        pv_dcn = deg_node[b] + cc_node[b];
        pv_dtn = dt_neigh[b * 64 + dn];
        pv_dc  = deg_neigh[b * 64 + dn] + cc_neigh[b * 64 + dn];
        pv_mk  = mask[b * 64 + dn];
    }

    for (; p < pairs; p += gridDim.x) {
        const int b = p * 2 + row;
        const float c_tn = pv_tn, c_dcn = pv_dcn;
        const float c_dtn = pv_dtn, c_dc = pv_dc;
        const u32 c_mk = pv_mk;

        // ---- node feature partial + mask count: thread (row, d=dn) ----
        float vv0 = c_tn * sTW[dn] + sTB[dn];
        float fb  = ((dn == 0) ? vv0 : __cosf(vv0)) + c_dcn * sNW[dn] + 2.0f * sNB[dn];
        float ss = fb * fb;
        float ms = c_mk ? 1.0f : 0.0f;
        const float mf = ms;
#pragma unroll
        for (int off = 16; off > 0; off >>= 1) {
            ss += __shfl_xor_sync(0xffffffffu, ss, off);
            ms += __shfl_xor_sync(0xffffffffu, ms, off);
        }
        if (lane == 0) { sRedN[wid] = ss; sRedM[wid] = ms; }
        bar_row(row);                                      // (A) + sF/sWn guard
        float inv = rsqrtf(fmaxf(sRedN[row * 2] + sRedN[row * 2 + 1], 1e-24f));
        sNF[t] = fb * inv;

        // ---- neighbor feature: thread (row, n=dn) -> sF (tf32-rounded) ----
        {
            float ta = fabsf(c_dtn);
            float f[64]; float s0 = 0.f, s1 = 0.f, s2a = 0.f, s3 = 0.f;
#pragma unroll
            for (int d = 0; d < 64; d += 4) {
                float v0 = ta * sTW[d] + sTB[d];
                float v1 = ta * sTW[d + 1] + sTB[d + 1];
                float v2 = ta * sTW[d + 2] + sTB[d + 2];
                float v3 = ta * sTW[d + 3] + sTB[d + 3];
                float c0 = (d == 0) ? v0 : __cosf(v0);
                float c1 = __cosf(v1), c2 = __cosf(v2), c3 = __cosf(v3);
                float x0 = c0 + c_dc * sNW[d] + 2.0f * sNB[d];
                float x1 = c1 + c_dc * sNW[d + 1] + 2.0f * sNB[d + 1];
                float x2 = c2 + c_dc * sNW[d + 2] + 2.0f * sNB[d + 2];
                float x3 = c3 + c_dc * sNW[d + 3] + 2.0f * sNB[d + 3];
                f[d] = x0; f[d + 1] = x1; f[d + 2] = x2; f[d + 3] = x3;
                s0 += x0 * x0; s1 += x1 * x1; s2a += x2 * x2; s3 += x3 * x3;
            }
            float inv2 = rsqrtf(fmaxf((s0 + s1) + (s2a + s3), 1e-24f));
            float* frow = sF + (row * 64 + dn) * FPITCH;
#pragma unroll
            for (int q = 0; q < 16; ++q) {
                float4 v4;
                v4.x = __uint_as_float(to_tf32(f[4 * q + 0] * inv2));
                v4.y = __uint_as_float(to_tf32(f[4 * q + 1] * inv2));
                v4.z = __uint_as_float(to_tf32(f[4 * q + 2] * inv2));
                v4.w = __uint_as_float(to_tf32(f[4 * q + 3] * inv2));
                *(float4*)(frow + 4 * q) = v4;
            }
        }
        bar_row(row);                                      // (B) sNF+sF visible

        // ---- prefetch next iteration ----
        {
            int pn = p + gridDim.x;
            if (pn < pairs) {
                int bn = pn * 2 + row;
                pv_tn  = fabsf(dt_node[bn]);
                pv_dcn = deg_node[bn] + cc_node[bn];
                pv_dtn = dt_neigh[bn * 64 + dn];
                pv_dc  = deg_neigh[bn * 64 + dn] + cc_neigh[bn * 64 + dn];
                pv_mk  = mask[bn * 64 + dn];
            }
        }

        // ---- a[e] = node_f . W1[:,e]: thread (row, e=dn) ----
        {
            float acc = 0.f;
#pragma unroll
            for (int d = 0; d < 64; ++d) acc += sNF[row * 64 + d] * sW1[d * 64 + dn];
            sAE[t] = acc;
        }
        bar_row(row);                                      // (C) sAE visible

        // ---- MMA: warp covers 32 neighbors (2 M-tiles) x 64 e x 64 d ----
        float cacc[2][8][4];
#pragma unroll
        for (int mt = 0; mt < 2; ++mt)
#pragma unroll
            for (int nt = 0; nt < 8; ++nt)
#pragma unroll
                for (int c = 0; c < 4; ++c) cacc[mt][nt][c] = 0.f;

        const float* fbase = sF + (mrow * 64 + mhalf * 32) * FPITCH;
#pragma unroll
        for (int kt = 0; kt < 8; ++kt) {
            u32 a[2][4];
#pragma unroll
            for (int mt = 0; mt < 2; ++mt) {
                const float* ap = fbase + mt * 16 * FPITCH + kt * 8;
                a[mt][0] = __float_as_uint(ap[g * FPITCH + tq]);
                a[mt][1] = __float_as_uint(ap[(g + 8) * FPITCH + tq]);
                a[mt][2] = __float_as_uint(ap[g * FPITCH + tq + 4]);
                a[mt][3] = __float_as_uint(ap[(g + 8) * FPITCH + tq + 4]);
            }
#pragma unroll
            for (int nt = 0; nt < 8; ++nt) {
                float2 bb = sBF[(kt * 8 + nt) * 32 + lane];
                u32 b0 = __float_as_uint(bb.x), b1 = __float_as_uint(bb.y);
                mma8(cacc[0][nt], a[0], b0, b1);
                mma8(cacc[1][nt], a[1], b0, b1);
            }
        }

        // ---- epilogue: att = sum_e v[e]*tanh(a[e] + proj[n][e]) ----
        {
            const float* aE = sAE + mrow * 64;
            float attv[2][2] = {{0.f, 0.f}, {0.f, 0.f}};
#pragma unroll
            for (int nt = 0; nt < 8; ++nt) {
                float v0 = sV[nt * 8 + 2 * tq], v1 = sV[nt * 8 + 2 * tq + 1];
                float a0 = aE[nt * 8 + 2 * tq], a1 = aE[nt * 8 + 2 * tq + 1];
#pragma unroll
                for (int mt = 0; mt < 2; ++mt) {
                    attv[mt][0] += v0 * tanh_fast(a0 + cacc[mt][nt][0])
                                 + v1 * tanh_fast(a1 + cacc[mt][nt][1]);
                    attv[mt][1] += v0 * tanh_fast(a0 + cacc[mt][nt][2])
                                 + v1 * tanh_fast(a1 + cacc[mt][nt][3]);
                }
            }
#pragma unroll
            for (int mt = 0; mt < 2; ++mt)
#pragma unroll
                for (int r2 = 0; r2 < 2; ++r2) {
                    float x = attv[mt][r2];
                    x += __shfl_xor_sync(0xffffffffu, x, 1);
                    x += __shfl_xor_sync(0xffffffffu, x, 2);
                    if (tq == 0)
                        sAtt[mrow * 64 + mhalf * 32 + mt * 16 + r2 * 8 + g] = x;
                }
        }
        bar_row(row);                                      // (D) sAtt visible

        // ---- score / mask / normalize: thread (row, n=dn) ----
        float at = sAtt[t];
        float ts = 1.0f / (1.0f + 2.0f * c_dtn);           // Decayer(2,'rev')
        float ls = (ts > 0.f) ? ts : 0.01f * ts;           // leaky_relu
        float sc = ls * at;
        float nin = fmaxf(sRedM[row * 2] + sRedM[row * 2 + 1], 1.0f);
        sWn[t] = mf * sc / nin;
        bar_row(row);                                      // (E) sWn visible

        // ---- aggregation: thread (row, d=dn) ----
        {
            float a0 = 0.f, a1 = 0.f, a2 = 0.f, a3 = 0.f;
            const float* fr = sF + row * 64 * FPITCH;
            const float* wn = sWn + row * 64;
#pragma unroll
            for (int n = 0; n < 64; n += 4) {
                a0 += wn[n]     * fr[n * FPITCH + dn];
                a1 += wn[n + 1] * fr[(n + 1) * FPITCH + dn];
                a2 += wn[n + 2] * fr[(n + 2) * FPITCH + dn];
                a3 += wn[n + 3] * fr[(n + 3) * FPITCH + dn];
            }
            g_C[b * 128 + dn] = sNF[t];
            g_C[b * 128 + 64 + dn] = (a0 + a1) + (a2 + a3);
        }
        // barrier (A) of next iteration guards sF/sNF/sWn reuse
    }
}

// ---------------- kernel 2: out = relu([g_C | hist] @ W^T), tf32 MMA -------
// M=16384, N=128, K=256. CTA tile 64x128, BK=64, 256 threads (8 warps).
__global__ __launch_bounds__(256)
void k_gemm(const float* __restrict__ hist, float* __restrict__ out) {
    extern __shared__ __align__(16) float sg[];
    float* sA = sg;                        // [64][68]
    float2* sB = (float2*)(sg + 64 * 68);  // 128 tiles * 32 lanes per K-block

    const int m0 = blockIdx.x * 64;
    const int t = threadIdx.x;
    const int lane = t & 31, wid = t >> 5;
    const int mt_row = wid >> 1, nhalf = wid & 1;
    const int g = lane >> 2, tq = lane & 3;

    float acc[8][4];
#pragma unroll
    for (int nt = 0; nt < 8; ++nt)
#pragma unroll
        for (int c = 0; c < 4; ++c) acc[nt][c] = 0.f;

#pragma unroll
    for (int kb = 0; kb < 4; ++kb) {
        const float* src = (kb < 2) ? g_C : hist;
        const int koff = (kb & 1) * 64;
        __syncthreads();
#pragma unroll
        for (int i = 0; i < 4; ++i) {
            int s = t + i * 256;
            int r = s >> 4, k4 = (s & 15) * 4;
            float4 v = *(const float4*)(src + (m0 + r) * 128 + koff + k4);
            float4 w;
            w.x = __uint_as_float(to_tf32(v.x));
            w.y = __uint_as_float(to_tf32(v.y));
            w.z = __uint_as_float(to_tf32(v.z));
            w.w = __uint_as_float(to_tf32(v.w));
            *(float4*)(sA + r * 68 + k4) = w;
        }
        {
            const float4* wf = (const float4*)(g_WF + kb * 4096);
            float4* sb4 = (float4*)sB;
#pragma unroll
            for (int i = 0; i < 8; ++i) sb4[t + i * 256] = wf[t + i * 256];
        }
        __syncthreads();

#pragma unroll
        for (int ktl = 0; ktl < 8; ++ktl) {
            u32 a[4];
            const float* ap = sA + (mt_row * 16) * 68 + ktl * 8;
            a[0] = __float_as_uint(ap[g * 68 + tq]);
            a[1] = __float_as_uint(ap[(g + 8) * 68 + tq]);
            a[2] = __float_as_uint(ap[g * 68 + tq + 4]);
            a[3] = __float_as_uint(ap[(g + 8) * 68 + tq + 4]);
#pragma unroll
            for (int nt = 0; nt < 8; ++nt) {
                float2 bb = sB[(ktl * 16 + nhalf * 8 + nt) * 32 + lane];
                mma8(acc[nt], a, __float_as_uint(bb.x), __float_as_uint(bb.y));
            }
        }
    }

#pragma unroll
    for (int nt = 0; nt < 8; ++nt) {
        int r1 = m0 + mt_row * 16 + g;
        int cc = nhalf * 64 + nt * 8 + 2 * tq;
        float2 lo, hi;
        lo.x = fmaxf(acc[nt][0], 0.f); lo.y = fmaxf(acc[nt][1], 0.f);
        hi.x = fmaxf(acc[nt][2], 0.f); hi.y = fmaxf(acc[nt][3], 0.f);
        *(float2*)(out + r1 * 128 + cc) = lo;
        *(float2*)(out + (r1 + 8) * 128 + cc) = hi;
    }
}

// ---------------------------- launcher --------------------------------------
extern "C" void kernel_launch(void* const* d_in, const int* in_sizes, int n_in,
                              void* d_out, int out_size) {
    const float* dt_node   = (const float*)d_in[0];
    const float* deg_node  = (const float*)d_in[1];
    const float* cc_node   = (const float*)d_in[2];
    const float* dt_neigh  = (const float*)d_in[3];
    const float* deg_neigh = (const float*)d_in[4];
    const float* cc_neigh  = (const float*)d_in[5];
    const unsigned int* mask = (const unsigned int*)d_in[6];
    const float* hist      = (const float*)d_in[7];
    const float* t2v_w     = (const float*)d_in[8];
    const float* t2v_b     = (const float*)d_in[9];
    const float* node_w    = (const float*)d_in[10];
    const float* node_b    = (const float*)d_in[11];
    const float* att_W1    = (const float*)d_in[12];
    const float* att_W2    = (const float*)d_in[13];
    const float* att_v     = (const float*)d_in[14];
    const float* weight    = (const float*)d_in[15];
    float* out = (float*)d_out;

    const int B = in_sizes[0];   // 16384
    const int pairs = B / 2;

    static int smem_set = 0;
    if (!smem_set) {
        cudaFuncSetAttribute(k_rows, cudaFuncAttributeMaxDynamicSharedMemorySize,
                             SMEM_TOTAL);
        cudaFuncSetAttribute(k_gemm, cudaFuncAttributeMaxDynamicSharedMemorySize,
                             GEMM_SMEM);
        smem_set = 1;
    }

    k_rows<<<444, 128, SMEM_TOTAL>>>(dt_node, deg_node, cc_node, dt_neigh,
                                     deg_neigh, cc_neigh, mask, t2v_w, t2v_b,
                                     node_w, node_b, att_W1, att_W2, att_v,
                                     weight, pairs);
    k_gemm<<<B / 64, 256, GEMM_SMEM>>>(hist, out);
}

// round 17
// speedup vs baseline: 1.7670x; 1.2168x over previous
#include <cuda_runtime.h>

// Problem shape: B = 16384 rows, N = 64 neighbors, D = 64, H = 128
#define BROWS 16384

__device__ float g_C[BROWS * 128];     // [node_f | neigh_agg] per row
// Classifier weight in tf32 B-fragment layout (tile kt 0..31, nt 0..15)
__device__ float2 g_WF[512 * 32];

typedef unsigned long long u64;
typedef unsigned int u32;

// ---------------- helpers ----------------
__device__ __forceinline__ float tanh_fast(float x) {
    float y; asm("tanh.approx.f32 %0, %1;" : "=f"(y) : "f"(x)); return y;
}
__device__ __forceinline__ u32 to_tf32(float x) {
    u32 r; asm("cvt.rna.tf32.f32 %0, %1;" : "=r"(r) : "f"(x)); return r;
}
// pack two floats into bf16x2: lo = a, hi = b
__device__ __forceinline__ u32 packbf(float a, float b) {
    u32 r; asm("cvt.rn.bf16x2.f32 %0, %1, %2;" : "=r"(r) : "f"(b), "f"(a));
    return r;
}
// load one bf16 from shared and widen to f32
__device__ __forceinline__ float bf2f(const void* p) {
    unsigned short us = *(const unsigned short*)p;
    return __uint_as_float(((u32)us) << 16);
}
// m16n8k8 tf32 MMA (k_gemm)
__device__ __forceinline__ void mma8(float* c, const u32* a, u32 b0, u32 b1) {
    asm("mma.sync.aligned.m16n8k8.row.col.f32.tf32.tf32.f32 "
        "{%0,%1,%2,%3}, {%4,%5,%6,%7}, {%8,%9}, {%0,%1,%2,%3};"
        : "+f"(c[0]), "+f"(c[1]), "+f"(c[2]), "+f"(c[3])
        : "r"(a[0]), "r"(a[1]), "r"(a[2]), "r"(a[3]), "r"(b0), "r"(b1));
}
// m16n8k16 bf16 MMA (k_rows attention)
__device__ __forceinline__ void mmab(float* c, const u32* a, u32 b0, u32 b1) {
    asm("mma.sync.aligned.m16n8k16.row.col.f32.bf16.bf16.f32 "
        "{%0,%1,%2,%3}, {%4,%5,%6,%7}, {%8,%9}, {%0,%1,%2,%3};"
        : "+f"(c[0]), "+f"(c[1]), "+f"(c[2]), "+f"(c[3])
        : "r"(a[0]), "r"(a[1]), "r"(a[2]), "r"(a[3]), "r"(b0), "r"(b1));
}
// row-group barrier: syncs only the 2 warps owning `row`
__device__ __forceinline__ void bar_row(int row) {
    asm volatile("bar.sync %0, 64;" :: "r"(row + 1) : "memory");
}

// ---------------- SMEM layout for k_rows (dynamic, bytes) ----------------
// F tile rows: 144 bytes (72 bf16 slots; word addr = 36n + d/2 -> A-frag
// loads hit banks 4g+tq mod 32: conflict-free).
#define FROWB       144
#define OFF_F       0                         // 2*64*144 = 18432
#define OFF_BF      18432                     // W2 bf16 B-frags: 32*32*8 = 8192
#define OFF_W1      26624                     // 16384
#define OFF_NF      43008                     // 512  node_f [2][64]
#define OFF_AE      43520                     // 512  a = node_f@W1 [2][64]
#define OFF_ATT     44032                     // 512  att [2][64]
#define OFF_WN      44544                     // 512  w_n [2][64]
#define OFF_INV     45056                     // 512  inv-norm per neighbor
#define OFF_V       45568                     // 256
#define OFF_TW      45824
#define OFF_TB      46080
#define OFF_NW      46336
#define OFF_NB      46592
#define OFF_RED     46848                     // 64 (norm[4] + mask[4])
#define SMEM_TOTAL  46912

// SMEM for k_gemm: A tile [64][68] floats + B fragments 4096 float2
#define GEMM_SMEM   (64 * 68 * 4 + 4096 * 8)  // 50176

// ---------------- kernel 1: persistent, 2 independent row pipelines --------
__global__ __launch_bounds__(128, 4)
void k_rows(const float* __restrict__ dt_node, const float* __restrict__ deg_node,
            const float* __restrict__ cc_node, const float* __restrict__ dt_neigh,
            const float* __restrict__ deg_neigh, const float* __restrict__ cc_neigh,
            const unsigned int* __restrict__ mask,
            const float* __restrict__ t2v_w, const float* __restrict__ t2v_b,
            const float* __restrict__ node_w, const float* __restrict__ node_b,
            const float* __restrict__ W1, const float* __restrict__ W2,
            const float* __restrict__ att_v, const float* __restrict__ Wcls,
            int pairs) {
    extern __shared__ __align__(16) char sm[];
    char*  smF = sm + OFF_F;
    uint2* sBF = (uint2*)(sm + OFF_BF);
    float* sW1 = (float*)(sm + OFF_W1);
    float* sNF = (float*)(sm + OFF_NF);
    float* sAE = (float*)(sm + OFF_AE);
    float* sAtt = (float*)(sm + OFF_ATT);
    float* sWn = (float*)(sm + OFF_WN);
    float* sInv = (float*)(sm + OFF_INV);
    float* sV  = (float*)(sm + OFF_V);
    float* sTW = (float*)(sm + OFF_TW);
    float* sTB = (float*)(sm + OFF_TB);
    float* sNW = (float*)(sm + OFF_NW);
    float* sNB = (float*)(sm + OFF_NB);
    float* sRedN = (float*)(sm + OFF_RED);       // [4] norm partials
    float* sRedM = (float*)(sm + OFF_RED) + 4;   // [4] mask-count partials

    const int t = threadIdx.x;
    const int lane = t & 31, wid = t >> 5;
    const int row = t >> 6;        // which row of the pair (0/1)
    const int dn  = t & 63;        // dim / neighbor index
    const int mrow = wid >> 1, mhalf = wid & 1;
    const int g = lane >> 2, tq = lane & 3;

    // ---- fold-in: classifier weight -> tf32 B-fragment layout (once) ----
    for (int e = blockIdx.x * 128 + t; e < 512 * 32; e += gridDim.x * 128) {
        int tile = e >> 5, ln = e & 31;
        int kt = tile >> 4, nt = tile & 15;
        int gg = ln >> 2, tqq = ln & 3;
        const float* wr = Wcls + (nt * 8 + gg) * 256 + kt * 8 + tqq;
        float2 v;
        v.x = __uint_as_float(to_tf32(wr[0]));
        v.y = __uint_as_float(to_tf32(wr[4]));
        g_WF[e] = v;
    }

    // ---- one-time init ----
    {   // W1 plain [d][e]
        const float4* src = (const float4*)W1;
        float4* dst = (float4*)sW1;
#pragma unroll
        for (int i = 0; i < 8; ++i) dst[t + i * 128] = src[t + i * 128];
    }
    // W2 -> bf16 B fragments: 32 tiles (kt 0..3, nt 0..7) x 32 lanes
#pragma unroll
    for (int i = 0; i < 8; ++i) {
        int e = t + i * 128;                 // 0..1023
        int tile = e >> 5, ln = e & 31;
        int kt = tile >> 3, nt = tile & 7;
        int gg = ln >> 2, tqq = ln & 3;
        int k0 = kt * 16 + 2 * tqq, nco = nt * 8 + gg;
        uint2 v;
        v.x = packbf(W2[k0 * 64 + nco],       W2[(k0 + 1) * 64 + nco]);
        v.y = packbf(W2[(k0 + 8) * 64 + nco], W2[(k0 + 9) * 64 + nco]);
        sBF[e] = v;
    }
    if (t < 64) { sV[t] = att_v[t]; sTW[t] = t2v_w[t]; sTB[t] = t2v_b[t];
                  sNW[t] = node_w[t]; sNB[t] = node_b[t]; }
    __syncthreads();

    // ---- prefetch first iteration's inputs ----
    int p = blockIdx.x;
    float pv_tn = 0.f, pv_dcn = 0.f, pv_dtn = 0.f, pv_dc = 0.f;
    u32 pv_mk = 0;
    if (p < pairs) {
        int b = p * 2 + row;
        pv_tn  = fabsf(dt_node[b]);
        pv_dcn = deg_node[b] + cc_node[b];
        pv_dtn = dt_neigh[b * 64 + dn];
        pv_dc  = deg_neigh[b * 64 + dn] + cc_neigh[b * 64 + dn];
        pv_mk  = mask[b * 64 + dn];
    }

    for (; p < pairs; p += gridDim.x) {
        const int b = p * 2 + row;
        const float c_tn = pv_tn, c_dcn = pv_dcn;
        const float c_dtn = pv_dtn, c_dc = pv_dc;
        const u32 c_mk = pv_mk;

        // ---- node feature partial + mask count: thread (row, d=dn) ----
        float vv0 = c_tn * sTW[dn] + sTB[dn];
        float fb  = ((dn == 0) ? vv0 : __cosf(vv0)) + c_dcn * sNW[dn] + 2.0f * sNB[dn];
        float ss = fb * fb;
        float ms = c_mk ? 1.0f : 0.0f;
        const float mf = ms;
#pragma unroll
        for (int off = 16; off > 0; off >>= 1) {
            ss += __shfl_xor_sync(0xffffffffu, ss, off);
            ms += __shfl_xor_sync(0xffffffffu, ms, off);
        }
        if (lane == 0) { sRedN[wid] = ss; sRedM[wid] = ms; }
        bar_row(row);                                      // (A) + sF/sWn guard
        float inv = rsqrtf(fmaxf(sRedN[row * 2] + sRedN[row * 2 + 1], 1e-24f));
        sNF[t] = fb * inv;

        // ---- neighbor feature (RAW, bf16): thread (row, n=dn) -> sF ----
        float inv2r;
        {
            float ta = fabsf(c_dtn);
            float s0 = 0.f, s1 = 0.f, s2a = 0.f, s3 = 0.f;
            char* frow = smF + (row * 64 + dn) * FROWB;
#pragma unroll
            for (int c8 = 0; c8 < 8; ++c8) {
                const int d0 = c8 * 8;
                float x[8];
#pragma unroll
                for (int j = 0; j < 8; ++j) {
                    float vv = ta * sTW[d0 + j] + sTB[d0 + j];
                    float cv = ((d0 + j) == 0) ? vv : __cosf(vv);
                    x[j] = cv + c_dc * sNW[d0 + j] + 2.0f * sNB[d0 + j];
                }
                s0 += x[0] * x[0] + x[4] * x[4];
                s1 += x[1] * x[1] + x[5] * x[5];
                s2a += x[2] * x[2] + x[6] * x[6];
                s3 += x[3] * x[3] + x[7] * x[7];
                uint4 pk;
                pk.x = packbf(x[0], x[1]); pk.y = packbf(x[2], x[3]);
                pk.z = packbf(x[4], x[5]); pk.w = packbf(x[6], x[7]);
                *(uint4*)(frow + d0 * 2) = pk;
            }
            inv2r = rsqrtf(fmaxf((s0 + s1) + (s2a + s3), 1e-24f));
            sInv[t] = inv2r;
        }
        bar_row(row);                                      // (B) sNF/sF/sInv

        // ---- prefetch next iteration ----
        {
            int pn = p + gridDim.x;
            if (pn < pairs) {
                int bn = pn * 2 + row;
                pv_tn  = fabsf(dt_node[bn]);
                pv_dcn = deg_node[bn] + cc_node[bn];
                pv_dtn = dt_neigh[bn * 64 + dn];
                pv_dc  = deg_neigh[bn * 64 + dn] + cc_neigh[bn * 64 + dn];
                pv_mk  = mask[bn * 64 + dn];
            }
        }

        // ---- a[e] = node_f . W1[:,e]: thread (row, e=dn) ----
        {
            float a0 = 0.f, a1 = 0.f, a2 = 0.f, a3 = 0.f;
            const float* nf = sNF + row * 64;
#pragma unroll
            for (int d = 0; d < 64; d += 4) {
                a0 += nf[d]     * sW1[d * 64 + dn];
                a1 += nf[d + 1] * sW1[(d + 1) * 64 + dn];
                a2 += nf[d + 2] * sW1[(d + 2) * 64 + dn];
                a3 += nf[d + 3] * sW1[(d + 3) * 64 + dn];
            }
            sAE[t] = (a0 + a1) + (a2 + a3);
        }
        bar_row(row);                                      // (C) sAE visible

        // ---- MMA (bf16 k16): warp covers 32 neighbors x 64 e x 64 d ----
        float cacc[2][8][4];
#pragma unroll
        for (int mt = 0; mt < 2; ++mt)
#pragma unroll
            for (int nt = 0; nt < 8; ++nt)
#pragma unroll
                for (int c = 0; c < 4; ++c) cacc[mt][nt][c] = 0.f;

        const char* fbase = smF + (mrow * 64 + mhalf * 32) * FROWB;
#pragma unroll
        for (int kt = 0; kt < 4; ++kt) {
            u32 a[2][4];
#pragma unroll
            for (int mt = 0; mt < 2; ++mt) {
                const char* ap = fbase + mt * 16 * FROWB + kt * 32 + tq * 4;
                a[mt][0] = *(const u32*)(ap + g * FROWB);
                a[mt][1] = *(const u32*)(ap + (g + 8) * FROWB);
                a[mt][2] = *(const u32*)(ap + g * FROWB + 16);
                a[mt][3] = *(const u32*)(ap + (g + 8) * FROWB + 16);
            }
#pragma unroll
            for (int nt = 0; nt < 8; ++nt) {
                uint2 bb = sBF[(kt * 8 + nt) * 32 + lane];
                mmab(cacc[0][nt], a[0], bb.x, bb.y);
                mmab(cacc[1][nt], a[1], bb.x, bb.y);
            }
        }

        // ---- epilogue: att = sum_e v[e]*tanh(a[e] + inv2[n]*raw_proj) ----
        {
            const float* aE = sAE + mrow * 64;
            float i0[2], i1[2];
#pragma unroll
            for (int mt = 0; mt < 2; ++mt) {
                int nb = mrow * 64 + mhalf * 32 + mt * 16 + g;
                i0[mt] = sInv[nb];
                i1[mt] = sInv[nb + 8];
            }
            float attv[2][2] = {{0.f, 0.f}, {0.f, 0.f}};
#pragma unroll
            for (int nt = 0; nt < 8; ++nt) {
                float v0 = sV[nt * 8 + 2 * tq], v1 = sV[nt * 8 + 2 * tq + 1];
                float a0 = aE[nt * 8 + 2 * tq], a1 = aE[nt * 8 + 2 * tq + 1];
#pragma unroll
                for (int mt = 0; mt < 2; ++mt) {
                    attv[mt][0] += v0 * tanh_fast(fmaf(cacc[mt][nt][0], i0[mt], a0))
                                 + v1 * tanh_fast(fmaf(cacc[mt][nt][1], i0[mt], a1));
                    attv[mt][1] += v0 * tanh_fast(fmaf(cacc[mt][nt][2], i1[mt], a0))
                                 + v1 * tanh_fast(fmaf(cacc[mt][nt][3], i1[mt], a1));
                }
            }
#pragma unroll
            for (int mt = 0; mt < 2; ++mt)
#pragma unroll
                for (int r2 = 0; r2 < 2; ++r2) {
                    float x = attv[mt][r2];
                    x += __shfl_xor_sync(0xffffffffu, x, 1);
                    x += __shfl_xor_sync(0xffffffffu, x, 2);
                    if (tq == 0)
                        sAtt[mrow * 64 + mhalf * 32 + mt * 16 + r2 * 8 + g] = x;
                }
        }
        bar_row(row);                                      // (D) sAtt visible

        // ---- score / mask / normalize: thread (row, n=dn) ----
        // inv2 folded in: aggregation uses raw bf16 F
        float at = sAtt[t];
        float ts = 1.0f / (1.0f + 2.0f * c_dtn);           // Decayer(2,'rev')
        float ls = (ts > 0.f) ? ts : 0.01f * ts;           // leaky_relu
        float sc = ls * at;
        float nin = fmaxf(sRedM[row * 2] + sRedM[row * 2 + 1], 1.0f);
        sWn[t] = mf * sc / nin * inv2r;
        bar_row(row);                                      // (E) sWn visible

        // ---- aggregation: thread (row, d=dn), bf16 raw F ----
        {
            float a0 = 0.f, a1 = 0.f, a2 = 0.f, a3 = 0.f;
            const char* fr = smF + row * 64 * FROWB + dn * 2;
            const float* wn = sWn + row * 64;
#pragma unroll
            for (int n = 0; n < 64; n += 4) {
                a0 += wn[n]     * bf2f(fr + n * FROWB);
                a1 += wn[n + 1] * bf2f(fr + (n + 1) * FROWB);
                a2 += wn[n + 2] * bf2f(fr + (n + 2) * FROWB);
                a3 += wn[n + 3] * bf2f(fr + (n + 3) * FROWB);
            }
            g_C[b * 128 + dn] = sNF[t];
            g_C[b * 128 + 64 + dn] = (a0 + a1) + (a2 + a3);
        }
        // barrier (A) of next iteration guards sF/sNF/sWn reuse
    }
}

// ---------------- kernel 2: out = relu([g_C | hist] @ W^T), tf32 MMA -------
// M=16384, N=128, K=256. CTA tile 64x128, BK=64, 256 threads (8 warps).
__global__ __launch_bounds__(256)
void k_gemm(const float* __restrict__ hist, float* __restrict__ out) {
    extern __shared__ __align__(16) float sg[];
    float* sA = sg;                        // [64][68]
    float2* sB = (float2*)(sg + 64 * 68);  // 128 tiles * 32 lanes per K-block

    const int m0 = blockIdx.x * 64;
    const int t = threadIdx.x;
    const int lane = t & 31, wid = t >> 5;
    const int mt_row = wid >> 1, nhalf = wid & 1;
    const int g = lane >> 2, tq = lane & 3;

    float acc[8][4];
#pragma unroll
    for (int nt = 0; nt < 8; ++nt)
#pragma unroll
        for (int c = 0; c < 4; ++c) acc[nt][c] = 0.f;

#pragma unroll
    for (int kb = 0; kb < 4; ++kb) {
        const float* src = (kb < 2) ? g_C : hist;
        const int koff = (kb & 1) * 64;
        __syncthreads();
#pragma unroll
        for (int i = 0; i < 4; ++i) {
            int s = t + i * 256;
            int r = s >> 4, k4 = (s & 15) * 4;
            float4 v = *(const float4*)(src + (m0 + r) * 128 + koff + k4);
            float4 w;
            w.x = __uint_as_float(to_tf32(v.x));
            w.y = __uint_as_float(to_tf32(v.y));
            w.z = __uint_as_float(to_tf32(v.z));
            w.w = __uint_as_float(to_tf32(v.w));
            *(float4*)(sA + r * 68 + k4) = w;
        }
        {
            const float4* wf = (const float4*)(g_WF + kb * 4096);
            float4* sb4 = (float4*)sB;
#pragma unroll
            for (int i = 0; i < 8; ++i) sb4[t + i * 256] = wf[t + i * 256];
        }
        __syncthreads();

#pragma unroll
        for (int ktl = 0; ktl < 8; ++ktl) {
            u32 a[4];
            const float* ap = sA + (mt_row * 16) * 68 + ktl * 8;
            a[0] = __float_as_uint(ap[g * 68 + tq]);
            a[1] = __float_as_uint(ap[(g + 8) * 68 + tq]);
            a[2] = __float_as_uint(ap[g * 68 + tq + 4]);
            a[3] = __float_as_uint(ap[(g + 8) * 68 + tq + 4]);
#pragma unroll
            for (int nt = 0; nt < 8; ++nt) {
                float2 bb = sB[(ktl * 16 + nhalf * 8 + nt) * 32 + lane];
                mma8(acc[nt], a, __float_as_uint(bb.x), __float_as_uint(bb.y));
            }
        }
    }

#pragma unroll
    for (int nt = 0; nt < 8; ++nt) {
        int r1 = m0 + mt_row * 16 + g;
        int cc = nhalf * 64 + nt * 8 + 2 * tq;
        float2 lo, hi;
        lo.x = fmaxf(acc[nt][0], 0.f); lo.y = fmaxf(acc[nt][1], 0.f);
        hi.x = fmaxf(acc[nt][2], 0.f); hi.y = fmaxf(acc[nt][3], 0.f);
        *(float2*)(out + r1 * 128 + cc) = lo;
        *(float2*)(out + (r1 + 8) * 128 + cc) = hi;
    }
}

// ---------------------------- launcher --------------------------------------
extern "C" void kernel_launch(void* const* d_in, const int* in_sizes, int n_in,
                              void* d_out, int out_size) {
    const float* dt_node   = (const float*)d_in[0];
    const float* deg_node  = (const float*)d_in[1];
    const float* cc_node   = (const float*)d_in[2];
    const float* dt_neigh  = (const float*)d_in[3];
    const float* deg_neigh = (const float*)d_in[4];
    const float* cc_neigh  = (const float*)d_in[5];
    const unsigned int* mask = (const unsigned int*)d_in[6];
    const float* hist      = (const float*)d_in[7];
    const float* t2v_w     = (const float*)d_in[8];
    const float* t2v_b     = (const float*)d_in[9];
    const float* node_w    = (const float*)d_in[10];
    const float* node_b    = (const float*)d_in[11];
    const float* att_W1    = (const float*)d_in[12];
    const float* att_W2    = (const float*)d_in[13];
    const float* att_v     = (const float*)d_in[14];
    const float* weight    = (const float*)d_in[15];
    float* out = (float*)d_out;

    const int B = in_sizes[0];   // 16384
    const int pairs = B / 2;

    static int smem_set = 0;
    if (!smem_set) {
        cudaFuncSetAttribute(k_rows, cudaFuncAttributeMaxDynamicSharedMemorySize,
                             SMEM_TOTAL);
        cudaFuncSetAttribute(k_gemm, cudaFuncAttributeMaxDynamicSharedMemorySize,
                             GEMM_SMEM);
        smem_set = 1;
    }

    k_rows<<<592, 128, SMEM_TOTAL>>>(dt_node, deg_node, cc_node, dt_neigh,
                                     deg_neigh, cc_neigh, mask, t2v_w, t2v_b,
                                     node_w, node_b, att_W1, att_W2, att_v,
                                     weight, pairs);
    k_gemm<<<B / 64, 256, GEMM_SMEM>>>(hist, out);
}